// round 14
// baseline (speedup 1.0000x reference)
#include <cuda_runtime.h>
#include <cuda_fp16.h>
#include <cstdint>

// ============================ problem constants ============================
#define BH   128
#define SEQ  1024
#define DIM  64
#define QT   64          // q rows per CTA (4 warps x 16 rows)
#define KT   128
#define NIT  8
#define NTHR 128
// fold 1/sqrt(64) * log2(e) into Q so scores are in log2 domain
#define QSCALE 0.1803368801111244f

// ============================ device scratch ============================
__device__ __half g_Kh[BH * SEQ * DIM];   // K, fp16
__device__ __half g_Lh[BH * SEQ * DIM];   // log_sigmoid(V), fp16
// permuted mask bits: [b][row][it][quad] u32
__device__ unsigned g_Mp[8 * SEQ * NIT * 4];

// ============================ PTX helpers ============================
__device__ __forceinline__ uint32_t smem_u32(const void* p) {
    uint32_t a;
    asm("{ .reg .u64 t; cvta.to.shared.u64 t, %1; cvt.u32.u64 %0, t; }"
        : "=r"(a) : "l"(p));
    return a;
}
__device__ __forceinline__ uint32_t swz(uint32_t o) { return o ^ ((o >> 3) & 0x70); }

__device__ __forceinline__ void ldmx4(uint32_t& r0, uint32_t& r1, uint32_t& r2,
                                      uint32_t& r3, uint32_t a) {
    asm volatile("ldmatrix.sync.aligned.m8n8.x4.shared.b16 {%0,%1,%2,%3}, [%4];"
        : "=r"(r0), "=r"(r1), "=r"(r2), "=r"(r3) : "r"(a));
}
__device__ __forceinline__ void ldmx4t(uint32_t& r0, uint32_t& r1, uint32_t& r2,
                                       uint32_t& r3, uint32_t a) {
    asm volatile("ldmatrix.sync.aligned.m8n8.x4.trans.shared.b16 {%0,%1,%2,%3}, [%4];"
        : "=r"(r0), "=r"(r1), "=r"(r2), "=r"(r3) : "r"(a));
}
// NON-volatile: pure register op; ptxas may pipeline freely
__device__ __forceinline__ void mma_f16(float* c, const uint32_t* a,
                                        uint32_t b0, uint32_t b1) {
    asm("mma.sync.aligned.m16n8k16.row.col.f32.f16.f16.f32 "
        "{%0,%1,%2,%3}, {%4,%5,%6,%7}, {%8,%9}, {%0,%1,%2,%3};"
        : "+f"(c[0]), "+f"(c[1]), "+f"(c[2]), "+f"(c[3])
        : "r"(a[0]), "r"(a[1]), "r"(a[2]), "r"(a[3]), "r"(b0), "r"(b1));
}
__device__ __forceinline__ uint32_t pack_h2(float lo, float hi) {
    uint32_t r;
    asm("cvt.rn.f16x2.f32 %0, %1, %2;" : "=r"(r) : "f"(hi), "f"(lo));
    return r;
}
__device__ __forceinline__ uint32_t h2ex2(uint32_t s) {
    uint32_t r;
    asm("ex2.approx.f16x2 %0, %1;" : "=r"(r) : "r"(s));
    return r;
}
__device__ __forceinline__ void cp16(uint32_t s, const void* g) {
    asm volatile("cp.async.cg.shared.global [%0], [%1], 16;" :: "r"(s), "l"(g));
}
#define CP_COMMIT() asm volatile("cp.async.commit_group;" ::: "memory")
#define CP_WAIT(n)  asm volatile("cp.async.wait_group %0;" :: "n"(n) : "memory")

// ============================ fused preprocessing ============================
#define MASK_BLOCKS 1024
__global__ void prep_all(const void* __restrict__ msrc,
                         const float4* __restrict__ K,
                         const float4* __restrict__ V) {
    if (blockIdx.x < MASK_BLOCKS) {
        int idx = blockIdx.x * 256 + threadIdx.x;
        int q = idx & 3;
        int chunk = idx >> 2;
        size_t ebase = (size_t)chunk * 128;
        uint4 d = ((const uint4*)msrc)[ebase / 16 + q];
        int ok = (d.x==0u||d.x==1u||d.x==0x3F800000u) && (d.y==0u||d.y==1u||d.y==0x3F800000u)
              && (d.z==0u||d.z==1u||d.z==0x3F800000u) && (d.w==0u||d.w==1u||d.w==0x3F800000u);
        int wide = __syncthreads_and(ok);
        unsigned w = 0;
        if (wide) {
            const uint2* s = (const uint2*)msrc + ebase / 2 + q;
#pragma unroll
            for (int i = 0; i < 16; i++) {
                uint2 a = s[i * 4];
                w |= ((a.x ? 1u : 0u) << (2 * i)) | ((a.y ? 1u : 0u) << (2 * i + 1));
            }
        } else {
            const unsigned short* s = (const unsigned short*)msrc + ebase / 2 + q;
#pragma unroll
            for (int i = 0; i < 16; i++) {
                unsigned v = s[i * 4];
                w |= (((v & 0xffu) ? 1u : 0u) << (2 * i)) | (((v >> 8) ? 1u : 0u) << (2 * i + 1));
            }
        }
        g_Mp[(size_t)chunk * 4 + q] = w;
    } else {
        int i = (blockIdx.x - MASK_BLOCKS) * 256 + threadIdx.x;
        float4 k = K[i];
        __half2* ko = (__half2*)g_Kh;
        ko[2 * i]     = __floats2half2_rn(k.x, k.y);
        ko[2 * i + 1] = __floats2half2_rn(k.z, k.w);
        float4 v = V[i];
        float a0 = fminf(v.x, 0.f) - log1pf(__expf(-fabsf(v.x)));
        float a1 = fminf(v.y, 0.f) - log1pf(__expf(-fabsf(v.y)));
        float a2 = fminf(v.z, 0.f) - log1pf(__expf(-fabsf(v.z)));
        float a3 = fminf(v.w, 0.f) - log1pf(__expf(-fabsf(v.w)));
        __half2* lo = (__half2*)g_Lh;
        lo[2 * i]     = __floats2half2_rn(a0, a1);
        lo[2 * i + 1] = __floats2half2_rn(a2, a3);
    }
}

// ============================ attention kernel ============================
// smem: Ks[2] 16KB each, Ls[2] 16KB each = 64KB
#define ST_K(s) ((s) * 16384)
#define ST_L(s) (32768 + (s) * 16384)
#define SMEM_BYTES 65536

__device__ __forceinline__ void prefetch_K(int st, int t, const __half* Kb,
                                           int k0, uint32_t sb) {
#pragma unroll
    for (int i = t; i < 1024; i += NTHR) {
        int r = i >> 3, j = i & 7;
        cp16(sb + ST_K(st) + swz(r * 128 + j * 16), Kb + (size_t)(k0 + r) * DIM + j * 8);
    }
}
__device__ __forceinline__ void prefetch_L(int st, int t, const __half* Lb,
                                           int k0, uint32_t sb) {
#pragma unroll
    for (int i = t; i < 1024; i += NTHR) {
        int r = i >> 3, j = i & 7;
        cp16(sb + ST_L(st) + swz(r * 128 + j * 16), Lb + (size_t)(k0 + r) * DIM + j * 8);
    }
}

// epilogue for one half: c[8][4] scores (log2 domain) -> masked fp16x2 P
#define EPI_HALF(hh, m0w, m1w)                                                  \
    do {                                                                        \
        const unsigned ma = (m0w) >> (16 * (hh)), mb = (m1w) >> (16 * (hh));    \
        _Pragma("unroll")                                                       \
        for (int j = 0; j < 8; j++) {                                           \
            uint32_t s01 = pack_h2(c[j][0], c[j][1]);                           \
            uint32_t s23 = pack_h2(c[j][2], c[j][3]);                           \
            unsigned ba = ma >> (2 * j), bb = mb >> (2 * j);                    \
            uint32_t k0m = ((ba & 1u) * 0xFFFFu) | ((ba & 2u) * 0x7FFF8000u);   \
            uint32_t k1m = ((bb & 1u) * 0xFFFFu) | ((bb & 2u) * 0x7FFF8000u);   \
            p2A[hh][j][0] = h2ex2(s01) & k0m;                                   \
            p2A[hh][j][1] = h2ex2(s23) & k1m;                                   \
        }                                                                       \
    } while (0)

__global__ void __launch_bounds__(NTHR, 3)
attn_kernel(const float* __restrict__ Q, float* __restrict__ out) {
    extern __shared__ char smem[];
    const uint32_t sb = smem_u32(smem);
    const int t = threadIdx.x, w = t >> 5, lane = t & 31;
    const int bh = blockIdx.y, q0 = blockIdx.x * QT;
    const int b = bh >> 4;

    const __half* Kbh = g_Kh + (size_t)bh * SEQ * DIM;
    const __half* Lbh = g_Lh + (size_t)bh * SEQ * DIM;

    // ---- Q tile: fp32 LDG -> fp16 (fold scale*log2e) -> smem (Ks0 area) ----
    {
        const float4* Qs = (const float4*)(Q + ((size_t)bh * SEQ + q0) * DIM);
#pragma unroll
        for (int i = t; i < 1024; i += NTHR) {   // 64 rows x 16 float4
            int r = i >> 4, j = i & 15;
            float4 q = Qs[i];
            uint2 hv;
            hv.x = pack_h2(q.x * QSCALE, q.y * QSCALE);
            hv.y = pack_h2(q.z * QSCALE, q.w * QSCALE);
            *(uint2*)(smem + ST_K(0) + swz(r * 128 + j * 8)) = hv;
        }
    }
    __syncthreads();

    const uint32_t xr = (uint32_t)(lane & 7) << 4;
    uint32_t qf[4][4];
    {
        uint32_t base = sb + ST_K(0) + (uint32_t)(16 * w + (lane & 15)) * 128;
        uint32_t ch = (uint32_t)(lane >> 4) << 4;
#pragma unroll
        for (int kd = 0; kd < 4; kd++)
            ldmx4(qf[kd][0], qf[kd][1], qf[kd][2], qf[kd][3],
                  base + (((uint32_t)kd * 32 + ch) ^ xr));
    }
    __syncthreads();

    // prologue prefetch: group c0={K0,L0}, c1={K1}
    prefetch_K(0, t, Kbh, 0, sb);
    prefetch_L(0, t, Lbh, 0, sb);
    CP_COMMIT();
    prefetch_K(1, t, Kbh, KT, sb);
    CP_COMMIT();
    CP_WAIT(1);
    __syncthreads();

    // mask pointers (quad = lane&3), rows 16w+(lane>>2) and +8
    const unsigned* mp0 = g_Mp + ((size_t)(b * 1024 + q0 + 16 * w + (lane >> 2)) * NIT) * 4 + (lane & 3);
    const unsigned* mp1 = mp0 + 8 * NIT * 4;

    const uint32_t rbK = (uint32_t)((lane & 7) + ((lane >> 4) << 3));
    const uint32_t csK = (uint32_t)(((lane >> 3) & 1) << 4);
    const uint32_t rbL = (uint32_t)((lane & 7) + (((lane >> 3) & 1) << 3));
    const uint32_t csL = (uint32_t)(((lane >> 4) & 1) << 4);
    const uint32_t bONE = (lane < 4) ? 0x3C003C00u : 0u;   // ones-column B frag

    float oacc[8][4];
    float oaccd[4];   // den column (virtual col 64)
#pragma unroll
    for (int j = 0; j < 8; j++)
#pragma unroll
        for (int x = 0; x < 4; x++) oacc[j][x] = 0.f;
#pragma unroll
    for (int x = 0; x < 4; x++) oaccd[x] = 0.f;

    uint32_t p2A[2][8][2];

    // ---- prologue: GEMM1(0) + epilogue(0) -> p2A ----
    {
        const unsigned m0w = mp0[0], m1w = mp1[0];
        const uint32_t baseK = sb + ST_K(0) + rbK * 128;
#pragma unroll
        for (int h = 0; h < 2; h++) {
            float c[8][4];
#pragma unroll
            for (int j = 0; j < 8; j++)
#pragma unroll
                for (int x = 0; x < 4; x++) c[j][x] = 0.f;
#pragma unroll
            for (int jp = 0; jp < 4; jp++) {
                const uint32_t ko = (uint32_t)(h * 4 + jp) * 2048;
                uint32_t bfr[4][4];
#pragma unroll
                for (int kd = 0; kd < 4; kd++)
                    ldmx4(bfr[kd][0], bfr[kd][1], bfr[kd][2], bfr[kd][3],
                          baseK + ko + (((uint32_t)kd * 32 + csK) ^ xr));
#pragma unroll
                for (int kd = 0; kd < 4; kd++) {
                    mma_f16(c[2 * jp],     qf[kd], bfr[kd][0], bfr[kd][1]);
                    mma_f16(c[2 * jp + 1], qf[kd], bfr[kd][2], bfr[kd][3]);
                }
            }
            EPI_HALF(h, m0w, m1w);
        }
    }

    // ---- main pipelined loop: it = 0..6 ----
    for (int it = 0; it < NIT - 1; it++) {
        __syncthreads();                       // A: stage reuse safety
        const unsigned mn0 = mp0[(it + 1) * 4], mn1 = mp1[(it + 1) * 4];
        if (it < NIT - 2) prefetch_K(it & 1, t, Kbh, (it + 2) * KT, sb);
        prefetch_L((it + 1) & 1, t, Lbh, (it + 1) * KT, sb);
        CP_COMMIT();
        CP_WAIT(1);
        __syncthreads();                       // B: visibility of K(it+1), L(it)

        const uint32_t baseK = sb + ST_K((it + 1) & 1) + rbK * 128;
        const uint32_t baseL = sb + ST_L(it & 1) + rbL * 128;

#pragma unroll
        for (int h = 0; h < 2; h++) {
            float c[8][4];
#pragma unroll
            for (int j = 0; j < 8; j++)
#pragma unroll
                for (int x = 0; x < 4; x++) c[j][x] = 0.f;

#pragma unroll
            for (int q = 0; q < 4; q++) {
                const uint32_t ko = (uint32_t)(h * 4 + q) * 2048;
                // GEMM2(it) quarter: O += P(it) @ L(it)
                uint32_t a[4] = {p2A[h][2 * q][0], p2A[h][2 * q][1],
                                 p2A[h][2 * q + 1][0], p2A[h][2 * q + 1][1]};
                uint32_t bl[4][4];
#pragma unroll
                for (int dp = 0; dp < 4; dp++)
                    ldmx4t(bl[dp][0], bl[dp][1], bl[dp][2], bl[dp][3],
                           baseL + ko + (((uint32_t)dp * 32 + csL) ^ xr));
#pragma unroll
                for (int dp = 0; dp < 4; dp++) {
                    mma_f16(oacc[2 * dp],     a, bl[dp][0], bl[dp][1]);
                    mma_f16(oacc[2 * dp + 1], a, bl[dp][2], bl[dp][3]);
                }
                mma_f16(oaccd, a, bONE, bONE);   // den column
                // GEMM1(it+1) quarter: c = Q @ K(it+1)^T
                uint32_t bfr[4][4];
#pragma unroll
                for (int kd = 0; kd < 4; kd++)
                    ldmx4(bfr[kd][0], bfr[kd][1], bfr[kd][2], bfr[kd][3],
                          baseK + ko + (((uint32_t)kd * 32 + csK) ^ xr));
#pragma unroll
                for (int kd = 0; kd < 4; kd++) {
                    mma_f16(c[2 * q],     qf[kd], bfr[kd][0], bfr[kd][1]);
                    mma_f16(c[2 * q + 1], qf[kd], bfr[kd][2], bfr[kd][3]);
                }
            }
            EPI_HALF(h, mn0, mn1);             // P(it+1) for this half
        }
    }

    // ---- tail: GEMM2(7) ----
    CP_WAIT(0);
    __syncthreads();
    {
        const uint32_t baseL = sb + ST_L((NIT - 1) & 1) + rbL * 128;
#pragma unroll
        for (int h = 0; h < 2; h++) {
#pragma unroll
            for (int q = 0; q < 4; q++) {
                const uint32_t ko = (uint32_t)(h * 4 + q) * 2048;
                uint32_t a[4] = {p2A[h][2 * q][0], p2A[h][2 * q][1],
                                 p2A[h][2 * q + 1][0], p2A[h][2 * q + 1][1]};
                uint32_t bl[4][4];
#pragma unroll
                for (int dp = 0; dp < 4; dp++)
                    ldmx4t(bl[dp][0], bl[dp][1], bl[dp][2], bl[dp][3],
                           baseL + ko + (((uint32_t)dp * 32 + csL) ^ xr));
#pragma unroll
                for (int dp = 0; dp < 4; dp++) {
                    mma_f16(oacc[2 * dp],     a, bl[dp][0], bl[dp][1]);
                    mma_f16(oacc[2 * dp + 1], a, bl[dp][2], bl[dp][3]);
                }
                mma_f16(oaccd, a, bONE, bONE);
            }
        }
    }

    // ---- final: den from ones-column, normalize, exp, store ----
    const float den0 = __shfl_sync(0xffffffffu, oaccd[0], lane & 28);
    const float den1 = __shfl_sync(0xffffffffu, oaccd[2], lane & 28);
    const float inv0 = 1.f / den0, inv1 = 1.f / den1;

    const int cb = 2 * (lane & 3);
    const int r0 = q0 + 16 * w + (lane >> 2);
    float* o0 = out + ((size_t)bh * SEQ + r0) * DIM + cb;
    float* o1 = o0 + 8 * DIM;
#pragma unroll
    for (int j = 0; j < 8; j++) {
        float2 v0, v1;
        v0.x = __expf(oacc[j][0] * inv0);
        v0.y = __expf(oacc[j][1] * inv0);
        v1.x = __expf(oacc[j][2] * inv1);
        v1.y = __expf(oacc[j][3] * inv1);
        *(float2*)(o0 + 8 * j) = v0;
        *(float2*)(o1 + 8 * j) = v1;
    }
}

// ============================ launch ============================
extern "C" void kernel_launch(void* const* d_in, const int* in_sizes, int n_in,
                              void* d_out, int out_size) {
    const float* Q = (const float*)d_in[0];
    const float* K = (const float*)d_in[1];
    const float* V = (const float*)d_in[2];
    const void*  M = d_in[3];
    float* out = (float*)d_out;

    prep_all<<<MASK_BLOCKS + 8192, 256>>>(M, (const float4*)K, (const float4*)V);

    cudaFuncSetAttribute(attn_kernel,
                         cudaFuncAttributeMaxDynamicSharedMemorySize, SMEM_BYTES);
    dim3 grid(SEQ / QT, BH);
    attn_kernel<<<grid, NTHR, SMEM_BYTES>>>(Q, out);
}

// round 15
// speedup vs baseline: 1.0301x; 1.0301x over previous
#include <cuda_runtime.h>
#include <cuda_fp16.h>
#include <cstdint>

// ============================ problem constants ============================
#define BH   128
#define SEQ  1024
#define DIM  64
#define QT   64          // q rows per CTA (4 warps x 16 rows)
#define KT   64          // k rows per iteration (small tile -> 32KB smem/CTA)
#define NIT  16
#define NTHR 128
// fold 1/sqrt(64) * log2(e) into Q so scores are in log2 domain
#define QSCALE 0.1803368801111244f

// ============================ device scratch ============================
__device__ __half g_Kh[BH * SEQ * DIM];   // K, fp16
__device__ __half g_Lh[BH * SEQ * DIM];   // log_sigmoid(V), fp16
// permuted mask bits: [b][row][chunk128][quad] u32
__device__ unsigned g_Mp[8 * SEQ * 8 * 4];

// ============================ PTX helpers ============================
__device__ __forceinline__ uint32_t smem_u32(const void* p) {
    uint32_t a;
    asm("{ .reg .u64 t; cvta.to.shared.u64 t, %1; cvt.u32.u64 %0, t; }"
        : "=r"(a) : "l"(p));
    return a;
}
__device__ __forceinline__ uint32_t swz(uint32_t o) { return o ^ ((o >> 3) & 0x70); }

__device__ __forceinline__ void ldmx4(uint32_t& r0, uint32_t& r1, uint32_t& r2,
                                      uint32_t& r3, uint32_t a) {
    asm volatile("ldmatrix.sync.aligned.m8n8.x4.shared.b16 {%0,%1,%2,%3}, [%4];"
        : "=r"(r0), "=r"(r1), "=r"(r2), "=r"(r3) : "r"(a));
}
__device__ __forceinline__ void ldmx4t(uint32_t& r0, uint32_t& r1, uint32_t& r2,
                                       uint32_t& r3, uint32_t a) {
    asm volatile("ldmatrix.sync.aligned.m8n8.x4.trans.shared.b16 {%0,%1,%2,%3}, [%4];"
        : "=r"(r0), "=r"(r1), "=r"(r2), "=r"(r3) : "r"(a));
}
// NON-volatile: pure register op; ptxas may pipeline freely
__device__ __forceinline__ void mma_f16(float* c, const uint32_t* a,
                                        uint32_t b0, uint32_t b1) {
    asm("mma.sync.aligned.m16n8k16.row.col.f32.f16.f16.f32 "
        "{%0,%1,%2,%3}, {%4,%5,%6,%7}, {%8,%9}, {%0,%1,%2,%3};"
        : "+f"(c[0]), "+f"(c[1]), "+f"(c[2]), "+f"(c[3])
        : "r"(a[0]), "r"(a[1]), "r"(a[2]), "r"(a[3]), "r"(b0), "r"(b1));
}
__device__ __forceinline__ uint32_t pack_h2(float lo, float hi) {
    uint32_t r;
    asm("cvt.rn.f16x2.f32 %0, %1, %2;" : "=r"(r) : "f"(hi), "f"(lo));
    return r;
}
__device__ __forceinline__ uint32_t h2ex2(uint32_t s) {
    uint32_t r;
    asm("ex2.approx.f16x2 %0, %1;" : "=r"(r) : "r"(s));
    return r;
}
__device__ __forceinline__ void cp16(uint32_t s, const void* g) {
    asm volatile("cp.async.cg.shared.global [%0], [%1], 16;" :: "r"(s), "l"(g));
}
#define CP_COMMIT() asm volatile("cp.async.commit_group;" ::: "memory")
#define CP_WAIT(n)  asm volatile("cp.async.wait_group %0;" :: "n"(n) : "memory")

// ============================ fused preprocessing ============================
#define MASK_BLOCKS 1024
__global__ void prep_all(const void* __restrict__ msrc,
                         const float4* __restrict__ K,
                         const float4* __restrict__ V) {
    if (blockIdx.x < MASK_BLOCKS) {
        int idx = blockIdx.x * 256 + threadIdx.x;
        int q = idx & 3;
        int chunk = idx >> 2;
        size_t ebase = (size_t)chunk * 128;
        uint4 d = ((const uint4*)msrc)[ebase / 16 + q];
        int ok = (d.x==0u||d.x==1u||d.x==0x3F800000u) && (d.y==0u||d.y==1u||d.y==0x3F800000u)
              && (d.z==0u||d.z==1u||d.z==0x3F800000u) && (d.w==0u||d.w==1u||d.w==0x3F800000u);
        int wide = __syncthreads_and(ok);
        unsigned w = 0;
        if (wide) {
            const uint2* s = (const uint2*)msrc + ebase / 2 + q;
#pragma unroll
            for (int i = 0; i < 16; i++) {
                uint2 a = s[i * 4];
                w |= ((a.x ? 1u : 0u) << (2 * i)) | ((a.y ? 1u : 0u) << (2 * i + 1));
            }
        } else {
            const unsigned short* s = (const unsigned short*)msrc + ebase / 2 + q;
#pragma unroll
            for (int i = 0; i < 16; i++) {
                unsigned v = s[i * 4];
                w |= (((v & 0xffu) ? 1u : 0u) << (2 * i)) | (((v >> 8) ? 1u : 0u) << (2 * i + 1));
            }
        }
        g_Mp[(size_t)chunk * 4 + q] = w;
    } else {
        int i = (blockIdx.x - MASK_BLOCKS) * 256 + threadIdx.x;
        float4 k = K[i];
        __half2* ko = (__half2*)g_Kh;
        ko[2 * i]     = __floats2half2_rn(k.x, k.y);
        ko[2 * i + 1] = __floats2half2_rn(k.z, k.w);
        float4 v = V[i];
        float a0 = fminf(v.x, 0.f) - log1pf(__expf(-fabsf(v.x)));
        float a1 = fminf(v.y, 0.f) - log1pf(__expf(-fabsf(v.y)));
        float a2 = fminf(v.z, 0.f) - log1pf(__expf(-fabsf(v.z)));
        float a3 = fminf(v.w, 0.f) - log1pf(__expf(-fabsf(v.w)));
        __half2* lo = (__half2*)g_Lh;
        lo[2 * i]     = __floats2half2_rn(a0, a1);
        lo[2 * i + 1] = __floats2half2_rn(a2, a3);
    }
}

// ============================ attention kernel ============================
// smem: 2 stages x (K 8KB + L 8KB) = 32KB; rows 128B, SW128 swizzle
#define ST_K(s) ((s) * 16384)
#define ST_L(s) ((s) * 16384 + 8192)
#define SMEM_BYTES 32768

__device__ __forceinline__ void prefetch_KL(int st, int t,
                                            const __half* Kb, const __half* Lb,
                                            int k0, uint32_t sb) {
#pragma unroll
    for (int i = t; i < 512; i += NTHR) {
        int r = i >> 3, j = i & 7;
        cp16(sb + ST_K(st) + swz(r * 128 + j * 16), Kb + (size_t)(k0 + r) * DIM + j * 8);
    }
#pragma unroll
    for (int i = t; i < 512; i += NTHR) {
        int r = i >> 3, j = i & 7;
        cp16(sb + ST_L(st) + swz(r * 128 + j * 16), Lb + (size_t)(k0 + r) * DIM + j * 8);
    }
}

__global__ void __launch_bounds__(NTHR, 4)
attn_kernel(const float* __restrict__ Q, float* __restrict__ out) {
    extern __shared__ char smem[];
    const uint32_t sb = smem_u32(smem);
    const int t = threadIdx.x, w = t >> 5, lane = t & 31;
    const int bh = blockIdx.y, q0 = blockIdx.x * QT;
    const int b = bh >> 4;

    const __half* Kbh = g_Kh + (size_t)bh * SEQ * DIM;
    const __half* Lbh = g_Lh + (size_t)bh * SEQ * DIM;

    // ---- Q tile: fp32 LDG -> fp16 (fold scale*log2e) -> smem (Ks0 area, 8KB) ----
    {
        const float4* Qs = (const float4*)(Q + ((size_t)bh * SEQ + q0) * DIM);
#pragma unroll
        for (int i = t; i < 1024; i += NTHR) {   // 64 rows x 16 float4
            int r = i >> 4, j = i & 15;
            float4 q = Qs[i];
            uint2 hv;
            hv.x = pack_h2(q.x * QSCALE, q.y * QSCALE);
            hv.y = pack_h2(q.z * QSCALE, q.w * QSCALE);
            *(uint2*)(smem + ST_K(0) + swz(r * 128 + j * 8)) = hv;
        }
    }
    __syncthreads();

    const uint32_t xr = (uint32_t)(lane & 7) << 4;
    uint32_t qf[4][4];
    {
        uint32_t base = sb + ST_K(0) + (uint32_t)(16 * w + (lane & 15)) * 128;
        uint32_t ch = (uint32_t)(lane >> 4) << 4;
#pragma unroll
        for (int kd = 0; kd < 4; kd++)
            ldmx4(qf[kd][0], qf[kd][1], qf[kd][2], qf[kd][3],
                  base + (((uint32_t)kd * 32 + ch) ^ xr));
    }
    __syncthreads();

    // mask pointers (quad = lane&3); rows 16w+(lane>>2), +8; 8 chunks/row, 4 words/chunk
    const unsigned* mp0 = g_Mp + ((size_t)(b * 1024 + q0 + 16 * w + (lane >> 2)) * 8) * 4 + (lane & 3);
    const unsigned* mp1 = mp0 + 8 * 8 * 4;

    const uint32_t rbK = (uint32_t)((lane & 7) + ((lane >> 4) << 3));
    const uint32_t csK = (uint32_t)(((lane >> 3) & 1) << 4);
    const uint32_t rbL = (uint32_t)((lane & 7) + (((lane >> 3) & 1) << 3));
    const uint32_t csL = (uint32_t)(((lane >> 4) & 1) << 4);
    const uint32_t bONE = (lane < 4) ? 0x3C003C00u : 0u;   // ones-column B frag

    float oacc[8][4];
    float oaccd[4];   // den column
#pragma unroll
    for (int j = 0; j < 8; j++)
#pragma unroll
        for (int x = 0; x < 4; x++) oacc[j][x] = 0.f;
#pragma unroll
    for (int x = 0; x < 4; x++) oaccd[x] = 0.f;

    // prologue prefetch of tile 0
    prefetch_KL(0, t, Kbh, Lbh, 0, sb);
    CP_COMMIT();

    for (int it = 0; it < NIT; it++) {
        const int st = it & 1;
        __syncthreads();                 // all warps done reading stage st^1
        if (it < NIT - 1) {
            prefetch_KL(st ^ 1, t, Kbh, Lbh, (it + 1) * KT, sb);
            CP_COMMIT();
            CP_WAIT(1);
        } else {
            CP_WAIT(0);
        }
        __syncthreads();                 // stage st data visible to all

        const unsigned sh = (unsigned)(it & 1) * 16;
        const unsigned mw0 = mp0[(it >> 1) * 4] >> sh;
        const unsigned mw1 = mp1[(it >> 1) * 4] >> sh;
        const uint32_t baseK = sb + ST_K(st) + rbK * 128;
        const uint32_t baseL = sb + ST_L(st) + rbL * 128;

        // ---- GEMM1: S[16x64] = Q @ K^T ----
        float c[8][4];
#pragma unroll
        for (int j = 0; j < 8; j++)
#pragma unroll
            for (int x = 0; x < 4; x++) c[j][x] = 0.f;
#pragma unroll
        for (int jp = 0; jp < 4; jp++) {
            const uint32_t ko = (uint32_t)jp * 2048;
            uint32_t bfr[4][4];
#pragma unroll
            for (int kd = 0; kd < 4; kd++)
                ldmx4(bfr[kd][0], bfr[kd][1], bfr[kd][2], bfr[kd][3],
                      baseK + ko + (((uint32_t)kd * 32 + csK) ^ xr));
#pragma unroll
            for (int kd = 0; kd < 4; kd++) {
                mma_f16(c[2 * jp],     qf[kd], bfr[kd][0], bfr[kd][1]);
                mma_f16(c[2 * jp + 1], qf[kd], bfr[kd][2], bfr[kd][3]);
            }
        }

        // ---- epilogue: P = mask & 2^S (f16x2) ----
        uint32_t p2[8][2];
#pragma unroll
        for (int j = 0; j < 8; j++) {
            uint32_t s01 = pack_h2(c[j][0], c[j][1]);
            uint32_t s23 = pack_h2(c[j][2], c[j][3]);
            unsigned ba = mw0 >> (2 * j), bb = mw1 >> (2 * j);
            uint32_t k0m = ((ba & 1u) * 0xFFFFu) | ((ba & 2u) * 0x7FFF8000u);
            uint32_t k1m = ((bb & 1u) * 0xFFFFu) | ((bb & 2u) * 0x7FFF8000u);
            p2[j][0] = h2ex2(s01) & k0m;
            p2[j][1] = h2ex2(s23) & k1m;
        }

        // ---- GEMM2: O[16x64] += P @ L ----
#pragma unroll
        for (int kk = 0; kk < 4; kk++) {
            const uint32_t ko = (uint32_t)kk * 2048;
            uint32_t a[4] = {p2[2 * kk][0], p2[2 * kk][1],
                             p2[2 * kk + 1][0], p2[2 * kk + 1][1]};
            uint32_t bl[4][4];
#pragma unroll
            for (int dp = 0; dp < 4; dp++)
                ldmx4t(bl[dp][0], bl[dp][1], bl[dp][2], bl[dp][3],
                       baseL + ko + (((uint32_t)dp * 32 + csL) ^ xr));
#pragma unroll
            for (int dp = 0; dp < 4; dp++) {
                mma_f16(oacc[2 * dp],     a, bl[dp][0], bl[dp][1]);
                mma_f16(oacc[2 * dp + 1], a, bl[dp][2], bl[dp][3]);
            }
            mma_f16(oaccd, a, bONE, bONE);   // den column
        }
    }

    // ---- final: den from ones-column, normalize, exp, store ----
    const float den0 = __shfl_sync(0xffffffffu, oaccd[0], lane & 28);
    const float den1 = __shfl_sync(0xffffffffu, oaccd[2], lane & 28);
    const float inv0 = 1.f / den0, inv1 = 1.f / den1;

    const int cb = 2 * (lane & 3);
    const int r0 = q0 + 16 * w + (lane >> 2);
    float* o0 = out + ((size_t)bh * SEQ + r0) * DIM + cb;
    float* o1 = o0 + 8 * DIM;
#pragma unroll
    for (int j = 0; j < 8; j++) {
        float2 v0, v1;
        v0.x = __expf(oacc[j][0] * inv0);
        v0.y = __expf(oacc[j][1] * inv0);
        v1.x = __expf(oacc[j][2] * inv1);
        v1.y = __expf(oacc[j][3] * inv1);
        *(float2*)(o0 + 8 * j) = v0;
        *(float2*)(o1 + 8 * j) = v1;
    }
}

// ============================ launch ============================
extern "C" void kernel_launch(void* const* d_in, const int* in_sizes, int n_in,
                              void* d_out, int out_size) {
    const float* Q = (const float*)d_in[0];
    const float* K = (const float*)d_in[1];
    const float* V = (const float*)d_in[2];
    const void*  M = d_in[3];
    float* out = (float*)d_out;

    prep_all<<<MASK_BLOCKS + 8192, 256>>>(M, (const float4*)K, (const float4*)V);

    cudaFuncSetAttribute(attn_kernel,
                         cudaFuncAttributeMaxDynamicSharedMemorySize, SMEM_BYTES);
    dim3 grid(SEQ / QT, BH);
    attn_kernel<<<grid, NTHR, SMEM_BYTES>>>(Q, out);
}